// round 1
// baseline (speedup 1.0000x reference)
#include <cuda_runtime.h>
#include <math.h>

// Problem constants (fixed by the reference)
#define D_MODEL   1024
#define NUM_HEADS 16
#define DK        64
#define B_        2
#define S_        2048
#define M_ROWS    (B_ * S_)   // 4096

// ---------------------------------------------------------------------------
// Scratch: __device__ globals (allocation-free per harness rules).
// Q, K, V in head-major [B, H, S, DK]; A (attn ctx) in [B, S, D] layout.
// ---------------------------------------------------------------------------
__device__ float g_Q[(size_t)M_ROWS * D_MODEL];
__device__ float g_K[(size_t)M_ROWS * D_MODEL];
__device__ float g_V[(size_t)M_ROWS * D_MODEL];
__device__ float g_A[(size_t)M_ROWS * D_MODEL];

// ---------------------------------------------------------------------------
// GEMM:  C[M,N] = A[M,K] * W[N,K]^T      (einsum 'md,nd->mn')
// Tile 64x64, BK=32, 256 threads, 4x4 micro-tile per thread.
// split_heads != 0: write C to head-major layout [(b*H+h)*S + s]*DK + d
// ---------------------------------------------------------------------------
__global__ __launch_bounds__(256)
void gemm_nt(const float* __restrict__ A, const float* __restrict__ W,
             float* __restrict__ C, int split_heads)
{
    const int K = D_MODEL;
    __shared__ float As[32][65];   // [k][m]  (pad 65 -> conflict-free xpose store)
    __shared__ float Bs[32][65];   // [k][n]

    const int tid = threadIdx.x;
    const int tx  = tid & 15;
    const int ty  = tid >> 4;
    const int m0  = blockIdx.y * 64;
    const int n0  = blockIdx.x * 64;

    float acc[4][4];
#pragma unroll
    for (int i = 0; i < 4; i++)
#pragma unroll
        for (int j = 0; j < 4; j++) acc[i][j] = 0.f;

    for (int k0 = 0; k0 < K; k0 += 32) {
#pragma unroll
        for (int it = 0; it < 2; it++) {
            int idx = tid + it * 256;      // 0..511
            int r   = idx >> 3;            // row 0..63
            int c4  = idx & 7;             // float4 index within 32 k-cols
            float4 va = *(const float4*)(A + (size_t)(m0 + r) * K + k0 + c4 * 4);
            As[c4 * 4 + 0][r] = va.x; As[c4 * 4 + 1][r] = va.y;
            As[c4 * 4 + 2][r] = va.z; As[c4 * 4 + 3][r] = va.w;
            float4 vb = *(const float4*)(W + (size_t)(n0 + r) * K + k0 + c4 * 4);
            Bs[c4 * 4 + 0][r] = vb.x; Bs[c4 * 4 + 1][r] = vb.y;
            Bs[c4 * 4 + 2][r] = vb.z; Bs[c4 * 4 + 3][r] = vb.w;
        }
        __syncthreads();

#pragma unroll
        for (int k = 0; k < 32; k++) {
            float a[4], b[4];
#pragma unroll
            for (int i = 0; i < 4; i++) a[i] = As[k][ty * 4 + i];
#pragma unroll
            for (int j = 0; j < 4; j++) b[j] = Bs[k][tx * 4 + j];
#pragma unroll
            for (int i = 0; i < 4; i++)
#pragma unroll
                for (int j = 0; j < 4; j++) acc[i][j] = fmaf(a[i], b[j], acc[i][j]);
        }
        __syncthreads();
    }

    // epilogue
#pragma unroll
    for (int i = 0; i < 4; i++) {
        int m = m0 + ty * 4 + i;
#pragma unroll
        for (int j = 0; j < 4; j++) {
            int n = n0 + tx * 4 + j;
            if (split_heads) {
                int b = m >> 11;        // m / S_
                int s = m & (S_ - 1);
                int h = n >> 6;         // n / DK
                int d = n & (DK - 1);
                C[(((size_t)b * NUM_HEADS + h) * S_ + s) * DK + d] = acc[i][j];
            } else {
                C[(size_t)m * D_MODEL + n] = acc[i][j];
            }
        }
    }
}

// ---------------------------------------------------------------------------
// Causal flash attention, fp32. One block = one 64-row Q tile of one (b,h).
// 256 threads; each thread owns 4 rows x 4 cols of every 64x64 tile.
// Smem: Qs[d][m] 64x65, Ks[d][n] 64x65 (aliased as Ps[n][m] for P*V),
//       Vs[n][d] 64x64.
// ---------------------------------------------------------------------------
#define SMEM_ATTN_BYTES ((64 * 65 * 2 + 64 * 64) * 4)   // 49664

__global__ __launch_bounds__(256)
void attn_kernel(const float* __restrict__ Q, const float* __restrict__ Kg,
                 const float* __restrict__ Vg, float* __restrict__ Out)
{
    extern __shared__ float sm[];
    float* Qs = sm;                 // Qs[d*65 + m]
    float* Ks = sm + 64 * 65;       // Ks[d*65 + n]  / after S: Ps[n*65 + m]
    float* Vs = sm + 2 * 64 * 65;   // Vs[n*64 + d]

    const int bh = blockIdx.y;
    const int b  = bh >> 4;
    const int h  = bh & 15;
    const float* Qh = Q  + (size_t)bh * S_ * DK;
    const float* Kh = Kg + (size_t)bh * S_ * DK;
    const float* Vh = Vg + (size_t)bh * S_ * DK;

    const int q0  = blockIdx.x * 64;
    const int tid = threadIdx.x;
    const int tx  = tid & 15;
    const int ty  = tid >> 4;

    // load Q tile transposed -> Qs[d][m]
#pragma unroll
    for (int it = 0; it < 4; it++) {
        int idx = tid + it * 256;      // 0..1023
        int r   = idx >> 4;            // 0..63
        int c4  = idx & 15;            // 0..15
        float4 v = *(const float4*)(Qh + (size_t)(q0 + r) * DK + c4 * 4);
        Qs[(c4 * 4 + 0) * 65 + r] = v.x; Qs[(c4 * 4 + 1) * 65 + r] = v.y;
        Qs[(c4 * 4 + 2) * 65 + r] = v.z; Qs[(c4 * 4 + 3) * 65 + r] = v.w;
    }

    float m_i[4], l_i[4], acc[4][4];
#pragma unroll
    for (int i = 0; i < 4; i++) {
        m_i[i] = -1e30f; l_i[i] = 0.f;
#pragma unroll
        for (int j = 0; j < 4; j++) acc[i][j] = 0.f;
    }

    const float scale = 0.125f;   // 1/sqrt(64)

    for (int kt = 0; kt <= (int)blockIdx.x; kt++) {
        const int k0 = kt * 64;
        __syncthreads();   // Ks/Ps/Vs reuse from previous iter; Q stores on iter 0

        // load K tile transposed, V tile direct
#pragma unroll
        for (int it = 0; it < 4; it++) {
            int idx = tid + it * 256;
            int r   = idx >> 4;
            int c4  = idx & 15;
            float4 vk = *(const float4*)(Kh + (size_t)(k0 + r) * DK + c4 * 4);
            Ks[(c4 * 4 + 0) * 65 + r] = vk.x; Ks[(c4 * 4 + 1) * 65 + r] = vk.y;
            Ks[(c4 * 4 + 2) * 65 + r] = vk.z; Ks[(c4 * 4 + 3) * 65 + r] = vk.w;
            float4 vv = *(const float4*)(Vh + (size_t)(k0 + r) * DK + c4 * 4);
            *(float4*)(Vs + r * 64 + c4 * 4) = vv;
        }
        __syncthreads();

        // S = scale * Q K^T  (per-thread 4x4)
        float s[4][4];
#pragma unroll
        for (int i = 0; i < 4; i++)
#pragma unroll
            for (int j = 0; j < 4; j++) s[i][j] = 0.f;
#pragma unroll
        for (int k = 0; k < 64; k++) {
            float a[4], bb[4];
#pragma unroll
            for (int i = 0; i < 4; i++) a[i]  = Qs[k * 65 + ty * 4 + i];
#pragma unroll
            for (int j = 0; j < 4; j++) bb[j] = Ks[k * 65 + tx * 4 + j];
#pragma unroll
            for (int i = 0; i < 4; i++)
#pragma unroll
                for (int j = 0; j < 4; j++) s[i][j] = fmaf(a[i], bb[j], s[i][j]);
        }

        const bool diag = (kt == (int)blockIdx.x);
#pragma unroll
        for (int i = 0; i < 4; i++) {
            int qr = q0 + ty * 4 + i;
#pragma unroll
            for (int j = 0; j < 4; j++) {
                float v = s[i][j] * scale;
                if (diag && (k0 + tx * 4 + j > qr)) v = -1e30f;
                s[i][j] = v;
            }
        }

        // online softmax: row max / sum across the 16 tx threads (width-16 shfl)
        float rmax[4];
#pragma unroll
        for (int i = 0; i < 4; i++) {
            float r = s[i][0];
            r = fmaxf(r, s[i][1]); r = fmaxf(r, s[i][2]); r = fmaxf(r, s[i][3]);
            rmax[i] = r;
        }
#pragma unroll
        for (int off = 8; off >= 1; off >>= 1)
#pragma unroll
            for (int i = 0; i < 4; i++)
                rmax[i] = fmaxf(rmax[i], __shfl_xor_sync(0xffffffffu, rmax[i], off, 16));

        float p[4][4], rsum[4], corr[4];
#pragma unroll
        for (int i = 0; i < 4; i++) {
            float newm = fmaxf(m_i[i], rmax[i]);
            corr[i] = __expf(m_i[i] - newm);
            float rs = 0.f;
#pragma unroll
            for (int j = 0; j < 4; j++) {
                float e = __expf(s[i][j] - newm);
                p[i][j] = e; rs += e;
            }
            rsum[i] = rs;
            m_i[i]  = newm;
        }
#pragma unroll
        for (int off = 8; off >= 1; off >>= 1)
#pragma unroll
            for (int i = 0; i < 4; i++)
                rsum[i] += __shfl_xor_sync(0xffffffffu, rsum[i], off, 16);
#pragma unroll
        for (int i = 0; i < 4; i++) {
            l_i[i] = l_i[i] * corr[i] + rsum[i];
#pragma unroll
            for (int j = 0; j < 4; j++) acc[i][j] *= corr[i];
        }

        __syncthreads();   // everyone done reading Ks before it becomes Ps
        // P -> Ps[n][m]  (aliased onto Ks buffer)
#pragma unroll
        for (int i = 0; i < 4; i++)
#pragma unroll
            for (int j = 0; j < 4; j++)
                Ks[(tx * 4 + j) * 65 + (ty * 4 + i)] = p[i][j];
        __syncthreads();

        // O += P * V
#pragma unroll
        for (int k = 0; k < 64; k++) {
            float a[4], bb[4];
#pragma unroll
            for (int i = 0; i < 4; i++) a[i]  = Ks[k * 65 + ty * 4 + i];
#pragma unroll
            for (int j = 0; j < 4; j++) bb[j] = Vs[k * 64 + tx * 4 + j];
#pragma unroll
            for (int i = 0; i < 4; i++)
#pragma unroll
                for (int j = 0; j < 4; j++) acc[i][j] = fmaf(a[i], bb[j], acc[i][j]);
        }
    }

    // epilogue: write context in [B, S, D] layout (heads re-merged)
#pragma unroll
    for (int i = 0; i < 4; i++) {
        int qr = q0 + ty * 4 + i;
        float inv_l = 1.f / l_i[i];
#pragma unroll
        for (int j = 0; j < 4; j++) {
            Out[((size_t)b * S_ + qr) * D_MODEL + h * DK + tx * 4 + j] = acc[i][j] * inv_l;
        }
    }
}

// ---------------------------------------------------------------------------
// Launch
// ---------------------------------------------------------------------------
extern "C" void kernel_launch(void* const* d_in, const int* in_sizes, int n_in,
                              void* d_out, int out_size)
{
    (void)in_sizes; (void)n_in; (void)out_size;
    const float* x  = (const float*)d_in[0];
    const float* Wq = (const float*)d_in[1];
    const float* Wk = (const float*)d_in[2];
    const float* Wv = (const float*)d_in[3];
    const float* Wo = (const float*)d_in[4];
    float* out = (float*)d_out;

    float *pQ, *pK, *pV, *pA;
    cudaGetSymbolAddress((void**)&pQ, g_Q);
    cudaGetSymbolAddress((void**)&pK, g_K);
    cudaGetSymbolAddress((void**)&pV, g_V);
    cudaGetSymbolAddress((void**)&pA, g_A);

    cudaFuncSetAttribute(attn_kernel,
                         cudaFuncAttributeMaxDynamicSharedMemorySize,
                         SMEM_ATTN_BYTES);

    dim3 ggrid(D_MODEL / 64, M_ROWS / 64);   // (16, 64)

    gemm_nt<<<ggrid, 256>>>(x, Wq, pQ, 1);
    gemm_nt<<<ggrid, 256>>>(x, Wk, pK, 1);
    gemm_nt<<<ggrid, 256>>>(x, Wv, pV, 1);

    dim3 agrid(S_ / 64, B_ * NUM_HEADS);     // (32, 32)
    attn_kernel<<<agrid, 256, SMEM_ATTN_BYTES>>>(pQ, pK, pV, pA);

    gemm_nt<<<ggrid, 256>>>(pA, Wo, out, 0);
}

// round 3
// speedup vs baseline: 1.6615x; 1.6615x over previous
#include <cuda_runtime.h>
#include <cuda_bf16.h>
#include <mma.h>
#include <math.h>
#include <stdint.h>

using namespace nvcuda;

// Problem constants
#define D_MODEL   1024
#define NUM_HEADS 16
#define DK        64
#define B_        2
#define S_        2048
#define M_ROWS    (B_ * S_)   // 4096

// ===========================================================================
// Scratch (__device__ globals, allocation-free)
// ===========================================================================
__device__ __align__(128) float g_Q[(size_t)M_ROWS * D_MODEL];
__device__ __align__(128) float g_K[(size_t)M_ROWS * D_MODEL];
__device__ __align__(128) float g_V[(size_t)M_ROWS * D_MODEL];
__device__ __align__(128) float g_A[(size_t)M_ROWS * D_MODEL];

__device__ __align__(128) __nv_bfloat16 g_xhi[(size_t)M_ROWS * D_MODEL];
__device__ __align__(128) __nv_bfloat16 g_xlo[(size_t)M_ROWS * D_MODEL];
__device__ __align__(128) __nv_bfloat16 g_Whi[4][(size_t)D_MODEL * D_MODEL];
__device__ __align__(128) __nv_bfloat16 g_Wlo[4][(size_t)D_MODEL * D_MODEL];
__device__ __align__(128) __nv_bfloat16 g_Ahi[(size_t)M_ROWS * D_MODEL];
__device__ __align__(128) __nv_bfloat16 g_Alo[(size_t)M_ROWS * D_MODEL];

// ===========================================================================
// cp.async helpers (sm_80+, no arch-specific features)
// ===========================================================================
__device__ __forceinline__ uint32_t smem_u32(const void* p) {
    uint32_t a;
    asm("{ .reg .u64 t; cvta.to.shared.u64 t, %1; cvt.u32.u64 %0, t; }"
        : "=r"(a) : "l"(p));
    return a;
}
__device__ __forceinline__ void cp_async16(uint32_t dst, const void* src) {
    uint64_t gsrc = __cvta_generic_to_global(src);
    asm volatile("cp.async.cg.shared.global [%0], [%1], 16;" :: "r"(dst), "l"(gsrc));
}
__device__ __forceinline__ void cp_async_commit() {
    asm volatile("cp.async.commit_group;" ::: "memory");
}
template <int N>
__device__ __forceinline__ void cp_async_wait() {
    asm volatile("cp.async.wait_group %0;" :: "n"(N) : "memory");
}

// ===========================================================================
// fp32 -> (bf16 hi, bf16 lo) split
// ===========================================================================
__global__ __launch_bounds__(256)
void split_fp32(const float* __restrict__ in, __nv_bfloat16* __restrict__ hi,
                __nv_bfloat16* __restrict__ lo, int n4)
{
    int i = blockIdx.x * 256 + threadIdx.x;
    if (i >= n4) return;
    float4 v = ((const float4*)in)[i];
    __nv_bfloat16 h0 = __float2bfloat16_rn(v.x);
    __nv_bfloat16 h1 = __float2bfloat16_rn(v.y);
    __nv_bfloat16 h2 = __float2bfloat16_rn(v.z);
    __nv_bfloat16 h3 = __float2bfloat16_rn(v.w);
    __nv_bfloat16 l0 = __float2bfloat16_rn(v.x - __bfloat162float(h0));
    __nv_bfloat16 l1 = __float2bfloat16_rn(v.y - __bfloat162float(h1));
    __nv_bfloat16 l2 = __float2bfloat16_rn(v.z - __bfloat162float(h2));
    __nv_bfloat16 l3 = __float2bfloat16_rn(v.w - __bfloat162float(h3));
    ((__nv_bfloat162*)hi)[i * 2 + 0] = __nv_bfloat162(h0, h1);
    ((__nv_bfloat162*)hi)[i * 2 + 1] = __nv_bfloat162(h2, h3);
    ((__nv_bfloat162*)lo)[i * 2 + 0] = __nv_bfloat162(l0, l1);
    ((__nv_bfloat162*)lo)[i * 2 + 1] = __nv_bfloat162(l2, l3);
}

// ===========================================================================
// WMMA bf16x3 GEMM:  C[M,N=1024] = A[M,K=1024] * W[N,K]^T
//   C ~= Ahi*Whi^T + Ahi*Wlo^T + Alo*Whi^T   (fp32 accum)
// Block 128x128, BK=32, 256 thr (8 warps; warp tile 32x64 = 2x4 wmma frags).
// smem rows padded to 40 halves (80B) -> conflict-free wmma loads.
// ===========================================================================
#define BM 128
#define BN 128
#define BK 32
#define PAD_K 40
#define MAT_BYTES (BM * PAD_K * 2)          // 10240 per matrix
#define STG_BYTES (4 * MAT_BYTES)           // 40960 per stage
#define SMEM_GEMM (2 * STG_BYTES)           // 81920
#define NSTG (D_MODEL / BK)                 // 32

__global__ __launch_bounds__(256)
void gemm_wmma(const __nv_bfloat16* __restrict__ Ahi, const __nv_bfloat16* __restrict__ Alo,
               const __nv_bfloat16* __restrict__ Bhi, const __nv_bfloat16* __restrict__ Blo,
               float* __restrict__ C, int split_heads)
{
    extern __shared__ char smem[];
    const uint32_t sbase = smem_u32(smem);
    const int tid = threadIdx.x;
    const int wid = tid >> 5;
    const int warp_m = wid & 3;      // 0..3  -> m offset *32
    const int warp_n = wid >> 2;     // 0..1  -> n offset *64
    const int m0 = blockIdx.y * BM;
    const int n0 = blockIdx.x * BN;

    // async copy of one K-stage (all 4 matrices) into buffer s
    auto load_stage = [&](int c, int s) {
        const int k0 = c * BK;
        const uint32_t st = sbase + s * STG_BYTES;
        // each matrix: 128 rows x 32 halves = 512 uint4; 2 per thread
#pragma unroll
        for (int u = 0; u < 2; u++) {
            int idx = tid + u * 256;            // 0..511
            int r   = idx >> 2;                 // row 0..127
            int c8  = idx & 3;                  // 8-half group
            uint32_t soff = (uint32_t)(r * (PAD_K * 2) + c8 * 16);
            size_t ga = (size_t)(m0 + r) * D_MODEL + k0 + c8 * 8;
            size_t gb = (size_t)(n0 + r) * D_MODEL + k0 + c8 * 8;
            cp_async16(st + 0 * MAT_BYTES + soff, Ahi + ga);
            cp_async16(st + 1 * MAT_BYTES + soff, Alo + ga);
            cp_async16(st + 2 * MAT_BYTES + soff, Bhi + gb);
            cp_async16(st + 3 * MAT_BYTES + soff, Blo + gb);
        }
        cp_async_commit();
    };

    wmma::fragment<wmma::accumulator, 16, 16, 16, float> acc[2][4];
#pragma unroll
    for (int i = 0; i < 2; i++)
#pragma unroll
        for (int j = 0; j < 4; j++) wmma::fill_fragment(acc[i][j], 0.f);

    load_stage(0, 0);

    for (int c = 0; c < NSTG; c++) {
        const int s = c & 1;
        if (c + 1 < NSTG) load_stage(c + 1, s ^ 1);
        if (c + 1 < NSTG) cp_async_wait<1>(); else cp_async_wait<0>();
        __syncthreads();

        const __nv_bfloat16* sA_hi = (const __nv_bfloat16*)(smem + s * STG_BYTES);
        const __nv_bfloat16* sA_lo = sA_hi + BM * PAD_K;
        const __nv_bfloat16* sB_hi = sA_lo + BM * PAD_K;
        const __nv_bfloat16* sB_lo = sB_hi + BM * PAD_K;

#pragma unroll
        for (int ks = 0; ks < 2; ks++) {
            wmma::fragment<wmma::matrix_a, 16, 16, 16, __nv_bfloat16, wmma::row_major> a_hi[2], a_lo[2];
#pragma unroll
            for (int i = 0; i < 2; i++) {
                int mr = warp_m * 32 + i * 16;
                wmma::load_matrix_sync(a_hi[i], sA_hi + mr * PAD_K + ks * 16, PAD_K);
                wmma::load_matrix_sync(a_lo[i], sA_lo + mr * PAD_K + ks * 16, PAD_K);
            }
#pragma unroll
            for (int j = 0; j < 4; j++) {
                int nr = warp_n * 64 + j * 16;
                wmma::fragment<wmma::matrix_b, 16, 16, 16, __nv_bfloat16, wmma::col_major> b_hi, b_lo;
                wmma::load_matrix_sync(b_hi, sB_hi + nr * PAD_K + ks * 16, PAD_K);
                wmma::load_matrix_sync(b_lo, sB_lo + nr * PAD_K + ks * 16, PAD_K);
#pragma unroll
                for (int i = 0; i < 2; i++) {
                    wmma::mma_sync(acc[i][j], a_hi[i], b_hi, acc[i][j]);
                    wmma::mma_sync(acc[i][j], a_hi[i], b_lo, acc[i][j]);
                    wmma::mma_sync(acc[i][j], a_lo[i], b_hi, acc[i][j]);
                }
            }
        }
        __syncthreads();
    }

    // epilogue: store 16x16 tiles straight to gmem
    const int b = m0 >> 11;
#pragma unroll
    for (int i = 0; i < 2; i++) {
        int m = m0 + warp_m * 32 + i * 16;
        int sI = m & (S_ - 1);
#pragma unroll
        for (int j = 0; j < 4; j++) {
            int n = n0 + warp_n * 64 + j * 16;
            if (split_heads) {
                int h = n >> 6, d = n & 63;
                float* p = C + (((size_t)b * NUM_HEADS + h) * S_ + sI) * DK + d;
                wmma::store_matrix_sync(p, acc[i][j], DK, wmma::mem_row_major);
            } else {
                float* p = C + (size_t)m * D_MODEL + n;
                wmma::store_matrix_sync(p, acc[i][j], D_MODEL, wmma::mem_row_major);
            }
        }
    }
}

// ===========================================================================
// Causal flash attention, fp32 (unchanged — next round's target)
// ===========================================================================
#define SMEM_ATTN_BYTES ((64 * 65 * 2 + 64 * 64) * 4)   // 49664

__global__ __launch_bounds__(256)
void attn_kernel(const float* __restrict__ Q, const float* __restrict__ Kg,
                 const float* __restrict__ Vg, float* __restrict__ Out)
{
    extern __shared__ float sm[];
    float* Qs = sm;
    float* Ks = sm + 64 * 65;
    float* Vs = sm + 2 * 64 * 65;

    const int bh = blockIdx.y;
    const int b  = bh >> 4;
    const int h  = bh & 15;
    const float* Qh = Q  + (size_t)bh * S_ * DK;
    const float* Kh = Kg + (size_t)bh * S_ * DK;
    const float* Vh = Vg + (size_t)bh * S_ * DK;

    const int q0  = blockIdx.x * 64;
    const int tid = threadIdx.x;
    const int tx  = tid & 15;
    const int ty  = tid >> 4;

#pragma unroll
    for (int it = 0; it < 4; it++) {
        int idx = tid + it * 256;
        int r   = idx >> 4;
        int c4  = idx & 15;
        float4 v = *(const float4*)(Qh + (size_t)(q0 + r) * DK + c4 * 4);
        Qs[(c4 * 4 + 0) * 65 + r] = v.x; Qs[(c4 * 4 + 1) * 65 + r] = v.y;
        Qs[(c4 * 4 + 2) * 65 + r] = v.z; Qs[(c4 * 4 + 3) * 65 + r] = v.w;
    }

    float m_i[4], l_i[4], acc[4][4];
#pragma unroll
    for (int i = 0; i < 4; i++) {
        m_i[i] = -1e30f; l_i[i] = 0.f;
#pragma unroll
        for (int j = 0; j < 4; j++) acc[i][j] = 0.f;
    }

    const float scale = 0.125f;

    for (int kt = 0; kt <= (int)blockIdx.x; kt++) {
        const int k0 = kt * 64;
        __syncthreads();

#pragma unroll
        for (int it = 0; it < 4; it++) {
            int idx = tid + it * 256;
            int r   = idx >> 4;
            int c4  = idx & 15;
            float4 vk = *(const float4*)(Kh + (size_t)(k0 + r) * DK + c4 * 4);
            Ks[(c4 * 4 + 0) * 65 + r] = vk.x; Ks[(c4 * 4 + 1) * 65 + r] = vk.y;
            Ks[(c4 * 4 + 2) * 65 + r] = vk.z; Ks[(c4 * 4 + 3) * 65 + r] = vk.w;
            float4 vv = *(const float4*)(Vh + (size_t)(k0 + r) * DK + c4 * 4);
            *(float4*)(Vs + r * 64 + c4 * 4) = vv;
        }
        __syncthreads();

        float s[4][4];
#pragma unroll
        for (int i = 0; i < 4; i++)
#pragma unroll
            for (int j = 0; j < 4; j++) s[i][j] = 0.f;
#pragma unroll
        for (int k = 0; k < 64; k++) {
            float a[4], bb[4];
#pragma unroll
            for (int i = 0; i < 4; i++) a[i]  = Qs[k * 65 + ty * 4 + i];
#pragma unroll
            for (int j = 0; j < 4; j++) bb[j] = Ks[k * 65 + tx * 4 + j];
#pragma unroll
            for (int i = 0; i < 4; i++)
#pragma unroll
                for (int j = 0; j < 4; j++) s[i][j] = fmaf(a[i], bb[j], s[i][j]);
        }

        const bool diag = (kt == (int)blockIdx.x);
#pragma unroll
        for (int i = 0; i < 4; i++) {
            int qr = q0 + ty * 4 + i;
#pragma unroll
            for (int j = 0; j < 4; j++) {
                float v = s[i][j] * scale;
                if (diag && (k0 + tx * 4 + j > qr)) v = -1e30f;
                s[i][j] = v;
            }
        }

        float rmax[4];
#pragma unroll
        for (int i = 0; i < 4; i++) {
            float r = s[i][0];
            r = fmaxf(r, s[i][1]); r = fmaxf(r, s[i][2]); r = fmaxf(r, s[i][3]);
            rmax[i] = r;
        }
#pragma unroll
        for (int off = 8; off >= 1; off >>= 1)
#pragma unroll
            for (int i = 0; i < 4; i++)
                rmax[i] = fmaxf(rmax[i], __shfl_xor_sync(0xffffffffu, rmax[i], off, 16));

        float p[4][4], rsum[4], corr[4];
#pragma unroll
        for (int i = 0; i < 4; i++) {
            float newm = fmaxf(m_i[i], rmax[i]);
            corr[i] = __expf(m_i[i] - newm);
            float rs = 0.f;
#pragma unroll
            for (int j = 0; j < 4; j++) {
                float e = __expf(s[i][j] - newm);
                p[i][j] = e; rs += e;
            }
            rsum[i] = rs;
            m_i[i]  = newm;
        }
#pragma unroll
        for (int off = 8; off >= 1; off >>= 1)
#pragma unroll
            for (int i = 0; i < 4; i++)
                rsum[i] += __shfl_xor_sync(0xffffffffu, rsum[i], off, 16);
#pragma unroll
        for (int i = 0; i < 4; i++) {
            l_i[i] = l_i[i] * corr[i] + rsum[i];
#pragma unroll
            for (int j = 0; j < 4; j++) acc[i][j] *= corr[i];
        }

        __syncthreads();
#pragma unroll
        for (int i = 0; i < 4; i++)
#pragma unroll
            for (int j = 0; j < 4; j++)
                Ks[(tx * 4 + j) * 65 + (ty * 4 + i)] = p[i][j];
        __syncthreads();

#pragma unroll
        for (int k = 0; k < 64; k++) {
            float a[4], bb[4];
#pragma unroll
            for (int i = 0; i < 4; i++) a[i]  = Ks[k * 65 + ty * 4 + i];
#pragma unroll
            for (int j = 0; j < 4; j++) bb[j] = Vs[k * 64 + tx * 4 + j];
#pragma unroll
            for (int i = 0; i < 4; i++)
#pragma unroll
                for (int j = 0; j < 4; j++) acc[i][j] = fmaf(a[i], bb[j], acc[i][j]);
        }
    }

#pragma unroll
    for (int i = 0; i < 4; i++) {
        int qr = q0 + ty * 4 + i;
        float inv_l = 1.f / l_i[i];
#pragma unroll
        for (int j = 0; j < 4; j++) {
            Out[((size_t)b * S_ + qr) * D_MODEL + h * DK + tx * 4 + j] = acc[i][j] * inv_l;
        }
    }
}

// ===========================================================================
// Launch
// ===========================================================================
extern "C" void kernel_launch(void* const* d_in, const int* in_sizes, int n_in,
                              void* d_out, int out_size)
{
    (void)in_sizes; (void)n_in; (void)out_size;
    const float* x  = (const float*)d_in[0];
    const float* Wq = (const float*)d_in[1];
    const float* Wk = (const float*)d_in[2];
    const float* Wv = (const float*)d_in[3];
    const float* Wo = (const float*)d_in[4];
    float* out = (float*)d_out;

    float *pQ, *pK, *pV, *pA;
    __nv_bfloat16 *pxh, *pxl, *pWh, *pWl, *pAh, *pAl;
    cudaGetSymbolAddress((void**)&pQ,  g_Q);
    cudaGetSymbolAddress((void**)&pK,  g_K);
    cudaGetSymbolAddress((void**)&pV,  g_V);
    cudaGetSymbolAddress((void**)&pA,  g_A);
    cudaGetSymbolAddress((void**)&pxh, g_xhi);
    cudaGetSymbolAddress((void**)&pxl, g_xlo);
    cudaGetSymbolAddress((void**)&pWh, g_Whi);
    cudaGetSymbolAddress((void**)&pWl, g_Wlo);
    cudaGetSymbolAddress((void**)&pAh, g_Ahi);
    cudaGetSymbolAddress((void**)&pAl, g_Alo);

    cudaFuncSetAttribute(attn_kernel, cudaFuncAttributeMaxDynamicSharedMemorySize,
                         SMEM_ATTN_BYTES);
    cudaFuncSetAttribute(gemm_wmma, cudaFuncAttributeMaxDynamicSharedMemorySize,
                         SMEM_GEMM);

    const size_t WSZ = (size_t)D_MODEL * D_MODEL;
    const int nx4 = M_ROWS * D_MODEL / 4;
    const int nw4 = (int)(WSZ / 4);

    split_fp32<<<nx4 / 256, 256>>>(x,  pxh, pxl, nx4);
    split_fp32<<<nw4 / 256, 256>>>(Wq, pWh + 0 * WSZ, pWl + 0 * WSZ, nw4);
    split_fp32<<<nw4 / 256, 256>>>(Wk, pWh + 1 * WSZ, pWl + 1 * WSZ, nw4);
    split_fp32<<<nw4 / 256, 256>>>(Wv, pWh + 2 * WSZ, pWl + 2 * WSZ, nw4);
    split_fp32<<<nw4 / 256, 256>>>(Wo, pWh + 3 * WSZ, pWl + 3 * WSZ, nw4);

    dim3 ggrid(D_MODEL / BN, M_ROWS / BM);   // (8, 32)
    gemm_wmma<<<ggrid, 256, SMEM_GEMM>>>(pxh, pxl, pWh + 0 * WSZ, pWl + 0 * WSZ, pQ, 1);
    gemm_wmma<<<ggrid, 256, SMEM_GEMM>>>(pxh, pxl, pWh + 1 * WSZ, pWl + 1 * WSZ, pK, 1);
    gemm_wmma<<<ggrid, 256, SMEM_GEMM>>>(pxh, pxl, pWh + 2 * WSZ, pWl + 2 * WSZ, pV, 1);

    dim3 agrid(S_ / 64, B_ * NUM_HEADS);
    attn_kernel<<<agrid, 256, SMEM_ATTN_BYTES>>>(pQ, pK, pV, pA);

    split_fp32<<<nx4 / 256, 256>>>(pA, pAh, pAl, nx4);
    gemm_wmma<<<ggrid, 256, SMEM_GEMM>>>(pAh, pAl, pWh + 3 * WSZ, pWl + 3 * WSZ, out, 0);
}

// round 4
// speedup vs baseline: 2.0430x; 1.2296x over previous
#include <cuda_runtime.h>
#include <cuda_bf16.h>
#include <mma.h>
#include <math.h>
#include <stdint.h>

using namespace nvcuda;

// Problem constants
#define D_MODEL   1024
#define NUM_HEADS 16
#define DK        64
#define B_        2
#define S_        2048
#define M_ROWS    (B_ * S_)   // 4096

// ===========================================================================
// Scratch (__device__ globals, allocation-free)
// ===========================================================================
__device__ __align__(128) float g_Q[(size_t)M_ROWS * D_MODEL];
__device__ __align__(128) float g_K[(size_t)M_ROWS * D_MODEL];
__device__ __align__(128) float g_V[(size_t)M_ROWS * D_MODEL];
__device__ __align__(128) float g_A[(size_t)M_ROWS * D_MODEL];

__device__ __align__(128) __nv_bfloat16 g_xhi[(size_t)M_ROWS * D_MODEL];
__device__ __align__(128) __nv_bfloat16 g_xlo[(size_t)M_ROWS * D_MODEL];
__device__ __align__(128) __nv_bfloat16 g_Whi[4][(size_t)D_MODEL * D_MODEL];
__device__ __align__(128) __nv_bfloat16 g_Wlo[4][(size_t)D_MODEL * D_MODEL];
__device__ __align__(128) __nv_bfloat16 g_Ahi[(size_t)M_ROWS * D_MODEL];
__device__ __align__(128) __nv_bfloat16 g_Alo[(size_t)M_ROWS * D_MODEL];

// ===========================================================================
// helpers
// ===========================================================================
__device__ __forceinline__ uint32_t smem_u32(const void* p) {
    uint32_t a;
    asm("{ .reg .u64 t; cvta.to.shared.u64 t, %1; cvt.u32.u64 %0, t; }"
        : "=r"(a) : "l"(p));
    return a;
}
__device__ __forceinline__ void cp_async16(uint32_t dst, const void* src) {
    uint64_t gsrc = __cvta_generic_to_global(src);
    asm volatile("cp.async.cg.shared.global [%0], [%1], 16;" :: "r"(dst), "l"(gsrc));
}
__device__ __forceinline__ void cp_async_commit() {
    asm volatile("cp.async.commit_group;" ::: "memory");
}
template <int N>
__device__ __forceinline__ void cp_async_wait() {
    asm volatile("cp.async.wait_group %0;" :: "n"(N) : "memory");
}

// ===========================================================================
// fp32 -> (bf16 hi, bf16 lo) split
// ===========================================================================
__global__ __launch_bounds__(256)
void split_fp32(const float* __restrict__ in, __nv_bfloat16* __restrict__ hi,
                __nv_bfloat16* __restrict__ lo, int n4)
{
    int i = blockIdx.x * 256 + threadIdx.x;
    if (i >= n4) return;
    float4 v = ((const float4*)in)[i];
    __nv_bfloat16 h0 = __float2bfloat16_rn(v.x);
    __nv_bfloat16 h1 = __float2bfloat16_rn(v.y);
    __nv_bfloat16 h2 = __float2bfloat16_rn(v.z);
    __nv_bfloat16 h3 = __float2bfloat16_rn(v.w);
    __nv_bfloat16 l0 = __float2bfloat16_rn(v.x - __bfloat162float(h0));
    __nv_bfloat16 l1 = __float2bfloat16_rn(v.y - __bfloat162float(h1));
    __nv_bfloat16 l2 = __float2bfloat16_rn(v.z - __bfloat162float(h2));
    __nv_bfloat16 l3 = __float2bfloat16_rn(v.w - __bfloat162float(h3));
    ((__nv_bfloat162*)hi)[i * 2 + 0] = __nv_bfloat162(h0, h1);
    ((__nv_bfloat162*)hi)[i * 2 + 1] = __nv_bfloat162(h2, h3);
    ((__nv_bfloat162*)lo)[i * 2 + 0] = __nv_bfloat162(l0, l1);
    ((__nv_bfloat162*)lo)[i * 2 + 1] = __nv_bfloat162(l2, l3);
}

// ===========================================================================
// WMMA bf16x3 GEMM (unchanged from R3)
// ===========================================================================
#define BM 128
#define BN 128
#define BK 32
#define PAD_K 40
#define MAT_BYTES (BM * PAD_K * 2)
#define STG_BYTES (4 * MAT_BYTES)
#define SMEM_GEMM (2 * STG_BYTES)
#define NSTG (D_MODEL / BK)

__global__ __launch_bounds__(256)
void gemm_wmma(const __nv_bfloat16* __restrict__ Ahi, const __nv_bfloat16* __restrict__ Alo,
               const __nv_bfloat16* __restrict__ Bhi, const __nv_bfloat16* __restrict__ Blo,
               float* __restrict__ C, int split_heads)
{
    extern __shared__ char smem[];
    const uint32_t sbase = smem_u32(smem);
    const int tid = threadIdx.x;
    const int wid = tid >> 5;
    const int warp_m = wid & 3;
    const int warp_n = wid >> 2;
    const int m0 = blockIdx.y * BM;
    const int n0 = blockIdx.x * BN;

    auto load_stage = [&](int c, int s) {
        const int k0 = c * BK;
        const uint32_t st = sbase + s * STG_BYTES;
#pragma unroll
        for (int u = 0; u < 2; u++) {
            int idx = tid + u * 256;
            int r   = idx >> 2;
            int c8  = idx & 3;
            uint32_t soff = (uint32_t)(r * (PAD_K * 2) + c8 * 16);
            size_t ga = (size_t)(m0 + r) * D_MODEL + k0 + c8 * 8;
            size_t gb = (size_t)(n0 + r) * D_MODEL + k0 + c8 * 8;
            cp_async16(st + 0 * MAT_BYTES + soff, Ahi + ga);
            cp_async16(st + 1 * MAT_BYTES + soff, Alo + ga);
            cp_async16(st + 2 * MAT_BYTES + soff, Bhi + gb);
            cp_async16(st + 3 * MAT_BYTES + soff, Blo + gb);
        }
        cp_async_commit();
    };

    wmma::fragment<wmma::accumulator, 16, 16, 16, float> acc[2][4];
#pragma unroll
    for (int i = 0; i < 2; i++)
#pragma unroll
        for (int j = 0; j < 4; j++) wmma::fill_fragment(acc[i][j], 0.f);

    load_stage(0, 0);

    for (int c = 0; c < NSTG; c++) {
        const int s = c & 1;
        if (c + 1 < NSTG) load_stage(c + 1, s ^ 1);
        if (c + 1 < NSTG) cp_async_wait<1>(); else cp_async_wait<0>();
        __syncthreads();

        const __nv_bfloat16* sA_hi = (const __nv_bfloat16*)(smem + s * STG_BYTES);
        const __nv_bfloat16* sA_lo = sA_hi + BM * PAD_K;
        const __nv_bfloat16* sB_hi = sA_lo + BM * PAD_K;
        const __nv_bfloat16* sB_lo = sB_hi + BM * PAD_K;

#pragma unroll
        for (int ks = 0; ks < 2; ks++) {
            wmma::fragment<wmma::matrix_a, 16, 16, 16, __nv_bfloat16, wmma::row_major> a_hi[2], a_lo[2];
#pragma unroll
            for (int i = 0; i < 2; i++) {
                int mr = warp_m * 32 + i * 16;
                wmma::load_matrix_sync(a_hi[i], sA_hi + mr * PAD_K + ks * 16, PAD_K);
                wmma::load_matrix_sync(a_lo[i], sA_lo + mr * PAD_K + ks * 16, PAD_K);
            }
#pragma unroll
            for (int j = 0; j < 4; j++) {
                int nr = warp_n * 64 + j * 16;
                wmma::fragment<wmma::matrix_b, 16, 16, 16, __nv_bfloat16, wmma::col_major> b_hi, b_lo;
                wmma::load_matrix_sync(b_hi, sB_hi + nr * PAD_K + ks * 16, PAD_K);
                wmma::load_matrix_sync(b_lo, sB_lo + nr * PAD_K + ks * 16, PAD_K);
#pragma unroll
                for (int i = 0; i < 2; i++) {
                    wmma::mma_sync(acc[i][j], a_hi[i], b_hi, acc[i][j]);
                    wmma::mma_sync(acc[i][j], a_hi[i], b_lo, acc[i][j]);
                    wmma::mma_sync(acc[i][j], a_lo[i], b_hi, acc[i][j]);
                }
            }
        }
        __syncthreads();
    }

    const int b = m0 >> 11;
#pragma unroll
    for (int i = 0; i < 2; i++) {
        int m = m0 + warp_m * 32 + i * 16;
        int sI = m & (S_ - 1);
#pragma unroll
        for (int j = 0; j < 4; j++) {
            int n = n0 + warp_n * 64 + j * 16;
            if (split_heads) {
                int h = n >> 6, d = n & 63;
                float* p = C + (((size_t)b * NUM_HEADS + h) * S_ + sI) * DK + d;
                wmma::store_matrix_sync(p, acc[i][j], DK, wmma::mem_row_major);
            } else {
                float* p = C + (size_t)m * D_MODEL + n;
                wmma::store_matrix_sync(p, acc[i][j], D_MODEL, wmma::mem_row_major);
            }
        }
    }
}

// ===========================================================================
// WMMA bf16x3 causal flash attention.
// Block = one (b,h) x 64-row Q tile. 8 warps.
// S = Qhi*Khi^T + Qhi*Klo^T + Qlo*Khi^T  (fp32 acc, staged to smem)
// softmax fp32 in smem; P split to bf16 hi/lo; O += Phi*Vhi + Phi*Vlo + Plo*Vhi
// ===========================================================================
#define PB 72   // bf16 row pad (elems)
#define PF 68   // fp32 row pad (elems)

#define A_QHI 0
#define A_QLO (A_QHI + 64 * PB * 2)          //  9216
#define A_KHI (A_QLO + 64 * PB * 2)          // 18432
#define A_KLO (A_KHI + 64 * PB * 2)
#define A_VHI (A_KLO + 64 * PB * 2)
#define A_VLO (A_VHI + 64 * PB * 2)
#define A_PHI (A_VLO + 64 * PB * 2)
#define A_PLO (A_PHI + 64 * PB * 2)
#define A_SS  (A_PLO + 64 * PB * 2)          // fp32 64 x PF
#define A_O   (A_SS + 64 * PF * 4)
#define A_M   (A_O + 64 * PF * 4)
#define A_L   (A_M + 64 * 4)
#define SMEM_ATTN (A_L + 64 * 4)             // 109056

__device__ __forceinline__ void split_store(__nv_bfloat16* hi, __nv_bfloat16* lo,
                                            int off, float v) {
    __nv_bfloat16 h = __float2bfloat16_rn(v);
    hi[off] = h;
    lo[off] = __float2bfloat16_rn(v - __bfloat162float(h));
}

__global__ __launch_bounds__(256)
void attn_wmma(const float* __restrict__ Q, const float* __restrict__ Kg,
               const float* __restrict__ Vg, float* __restrict__ Out)
{
    extern __shared__ char smem[];
    __nv_bfloat16* Qhi = (__nv_bfloat16*)(smem + A_QHI);
    __nv_bfloat16* Qlo = (__nv_bfloat16*)(smem + A_QLO);
    __nv_bfloat16* Khi = (__nv_bfloat16*)(smem + A_KHI);
    __nv_bfloat16* Klo = (__nv_bfloat16*)(smem + A_KLO);
    __nv_bfloat16* Vhi = (__nv_bfloat16*)(smem + A_VHI);
    __nv_bfloat16* Vlo = (__nv_bfloat16*)(smem + A_VLO);
    __nv_bfloat16* Phi = (__nv_bfloat16*)(smem + A_PHI);
    __nv_bfloat16* Plo = (__nv_bfloat16*)(smem + A_PLO);
    float* Ss  = (float*)(smem + A_SS);
    float* Osm = (float*)(smem + A_O);
    float* Msm = (float*)(smem + A_M);
    float* Lsm = (float*)(smem + A_L);

    const int bh = blockIdx.y;
    const int b  = bh >> 4;
    const int h  = bh & 15;
    const float* Qh = Q  + (size_t)bh * S_ * DK;
    const float* Kh = Kg + (size_t)bh * S_ * DK;
    const float* Vh = Vg + (size_t)bh * S_ * DK;

    const int qt  = blockIdx.x;
    const int q0  = qt * 64;
    const int tid = threadIdx.x;
    const int wid = tid >> 5;
    const int wm  = (wid & 3) * 16;   // warp row offset
    const int wn  = (wid >> 2) * 32;  // warp col offset (2 frags)

    // init: load+split Q, zero O, init m/l
#pragma unroll
    for (int it = 0; it < 4; it++) {
        int idx = tid + it * 256;          // 0..1023
        int r   = idx >> 4;                // 0..63
        int c4  = idx & 15;                // float4 group
        float4 v = *(const float4*)(Qh + (size_t)(q0 + r) * DK + c4 * 4);
        int o = r * PB + c4 * 4;
        split_store(Qhi, Qlo, o + 0, v.x);
        split_store(Qhi, Qlo, o + 1, v.y);
        split_store(Qhi, Qlo, o + 2, v.z);
        split_store(Qhi, Qlo, o + 3, v.w);
    }
    for (int i = tid; i < 64 * PF; i += 256) Osm[i] = 0.f;
    if (tid < 64) { Msm[tid] = -1e30f; Lsm[tid] = 0.f; }

    const int row = tid >> 2;          // softmax row (0..63)
    const int qq  = tid & 3;           // quarter (16 cols)
    const float scale = 0.125f;

    for (int kt = 0; kt <= qt; kt++) {
        const int k0 = kt * 64;
        // ---- load + split K, V tiles ----
#pragma unroll
        for (int it = 0; it < 4; it++) {
            int idx = tid + it * 256;
            int r   = idx >> 4;
            int c4  = idx & 15;
            int o = r * PB + c4 * 4;
            float4 vk = *(const float4*)(Kh + (size_t)(k0 + r) * DK + c4 * 4);
            split_store(Khi, Klo, o + 0, vk.x);
            split_store(Khi, Klo, o + 1, vk.y);
            split_store(Khi, Klo, o + 2, vk.z);
            split_store(Khi, Klo, o + 3, vk.w);
            float4 vv = *(const float4*)(Vh + (size_t)(k0 + r) * DK + c4 * 4);
            split_store(Vhi, Vlo, o + 0, vv.x);
            split_store(Vhi, Vlo, o + 1, vv.y);
            split_store(Vhi, Vlo, o + 2, vv.z);
            split_store(Vhi, Vlo, o + 3, vv.w);
        }
        __syncthreads();   // (A) tiles ready; prev iter's O+= done

        // ---- S = Q K^T (bf16x3) ----
        {
            wmma::fragment<wmma::accumulator, 16, 16, 16, float> sfr[2];
            wmma::fill_fragment(sfr[0], 0.f);
            wmma::fill_fragment(sfr[1], 0.f);
#pragma unroll
            for (int dk = 0; dk < 4; dk++) {
                wmma::fragment<wmma::matrix_a, 16, 16, 16, __nv_bfloat16, wmma::row_major> ah, al;
                wmma::load_matrix_sync(ah, Qhi + wm * PB + dk * 16, PB);
                wmma::load_matrix_sync(al, Qlo + wm * PB + dk * 16, PB);
#pragma unroll
                for (int j = 0; j < 2; j++) {
                    wmma::fragment<wmma::matrix_b, 16, 16, 16, __nv_bfloat16, wmma::col_major> bh_, bl_;
                    wmma::load_matrix_sync(bh_, Khi + (wn + j * 16) * PB + dk * 16, PB);
                    wmma::load_matrix_sync(bl_, Klo + (wn + j * 16) * PB + dk * 16, PB);
                    wmma::mma_sync(sfr[j], ah, bh_, sfr[j]);
                    wmma::mma_sync(sfr[j], ah, bl_, sfr[j]);
                    wmma::mma_sync(sfr[j], al, bh_, sfr[j]);
                }
            }
            wmma::store_matrix_sync(Ss + wm * PF + wn,      sfr[0], PF, wmma::mem_row_major);
            wmma::store_matrix_sync(Ss + wm * PF + wn + 16, sfr[1], PF, wmma::mem_row_major);
        }
        __syncthreads();   // (B) S staged

        // ---- softmax: 4 threads per row, 16 cols each ----
        {
            const bool diag = (kt == qt);
            const int qrow = q0 + row;
            float sv[16];
            float vmax = -1e30f;
#pragma unroll
            for (int c = 0; c < 16; c++) {
                int col = qq * 16 + c;
                float v = Ss[row * PF + col] * scale;
                if (diag && (k0 + col > qrow)) v = -1e30f;
                sv[c] = v;
                vmax = fmaxf(vmax, v);
            }
            vmax = fmaxf(vmax, __shfl_xor_sync(0xffffffffu, vmax, 1, 4));
            vmax = fmaxf(vmax, __shfl_xor_sync(0xffffffffu, vmax, 2, 4));

            float mprev = Msm[row];
            float newm  = fmaxf(mprev, vmax);
            float corr  = __expf(mprev - newm);
            float rsum  = 0.f;
#pragma unroll
            for (int c = 0; c < 16; c++) {
                float p = __expf(sv[c] - newm);
                rsum += p;
                split_store(Phi, Plo, row * PB + qq * 16 + c, p);
            }
            rsum += __shfl_xor_sync(0xffffffffu, rsum, 1, 4);
            rsum += __shfl_xor_sync(0xffffffffu, rsum, 2, 4);
            if (qq == 0) {
                Msm[row] = newm;
                Lsm[row] = Lsm[row] * corr + rsum;
            }
            // rescale O rows
#pragma unroll
            for (int c = 0; c < 16; c++)
                Osm[row * PF + qq * 16 + c] *= corr;
        }
        __syncthreads();   // (C) P ready, O rescaled

        // ---- PV (bf16x3) -> Ss scratch ----
        {
            wmma::fragment<wmma::accumulator, 16, 16, 16, float> ofr[2];
            wmma::fill_fragment(ofr[0], 0.f);
            wmma::fill_fragment(ofr[1], 0.f);
#pragma unroll
            for (int dk = 0; dk < 4; dk++) {
                wmma::fragment<wmma::matrix_a, 16, 16, 16, __nv_bfloat16, wmma::row_major> ah, al;
                wmma::load_matrix_sync(ah, Phi + wm * PB + dk * 16, PB);
                wmma::load_matrix_sync(al, Plo + wm * PB + dk * 16, PB);
#pragma unroll
                for (int j = 0; j < 2; j++) {
                    wmma::fragment<wmma::matrix_b, 16, 16, 16, __nv_bfloat16, wmma::row_major> bh_, bl_;
                    wmma::load_matrix_sync(bh_, Vhi + (dk * 16) * PB + wn + j * 16, PB);
                    wmma::load_matrix_sync(bl_, Vlo + (dk * 16) * PB + wn + j * 16, PB);
                    wmma::mma_sync(ofr[j], ah, bh_, ofr[j]);
                    wmma::mma_sync(ofr[j], ah, bl_, ofr[j]);
                    wmma::mma_sync(ofr[j], al, bh_, ofr[j]);
                }
            }
            wmma::store_matrix_sync(Ss + wm * PF + wn,      ofr[0], PF, wmma::mem_row_major);
            wmma::store_matrix_sync(Ss + wm * PF + wn + 16, ofr[1], PF, wmma::mem_row_major);
        }
        __syncthreads();   // (D) PV staged; all V reads complete

        // ---- O += PV ----
#pragma unroll
        for (int c = 0; c < 16; c++)
            Osm[row * PF + qq * 16 + c] += Ss[row * PF + qq * 16 + c];
        // next iteration's (A) sync guards the O+= before Ss reuse
    }
    __syncthreads();

    // epilogue: normalize, write [B,S,D]
    {
        float inv_l = 1.f / Lsm[row];
        float* dst = Out + ((size_t)b * S_ + q0 + row) * D_MODEL + h * DK + qq * 16;
#pragma unroll
        for (int c = 0; c < 16; c++)
            dst[c] = Osm[row * PF + qq * 16 + c] * inv_l;
    }
}

// ===========================================================================
// Launch
// ===========================================================================
extern "C" void kernel_launch(void* const* d_in, const int* in_sizes, int n_in,
                              void* d_out, int out_size)
{
    (void)in_sizes; (void)n_in; (void)out_size;
    const float* x  = (const float*)d_in[0];
    const float* Wq = (const float*)d_in[1];
    const float* Wk = (const float*)d_in[2];
    const float* Wv = (const float*)d_in[3];
    const float* Wo = (const float*)d_in[4];
    float* out = (float*)d_out;

    float *pQ, *pK, *pV, *pA;
    __nv_bfloat16 *pxh, *pxl, *pWh, *pWl, *pAh, *pAl;
    cudaGetSymbolAddress((void**)&pQ,  g_Q);
    cudaGetSymbolAddress((void**)&pK,  g_K);
    cudaGetSymbolAddress((void**)&pV,  g_V);
    cudaGetSymbolAddress((void**)&pA,  g_A);
    cudaGetSymbolAddress((void**)&pxh, g_xhi);
    cudaGetSymbolAddress((void**)&pxl, g_xlo);
    cudaGetSymbolAddress((void**)&pWh, g_Whi);
    cudaGetSymbolAddress((void**)&pWl, g_Wlo);
    cudaGetSymbolAddress((void**)&pAh, g_Ahi);
    cudaGetSymbolAddress((void**)&pAl, g_Alo);

    cudaFuncSetAttribute(gemm_wmma, cudaFuncAttributeMaxDynamicSharedMemorySize,
                         SMEM_GEMM);
    cudaFuncSetAttribute(attn_wmma, cudaFuncAttributeMaxDynamicSharedMemorySize,
                         SMEM_ATTN);

    const size_t WSZ = (size_t)D_MODEL * D_MODEL;
    const int nx4 = M_ROWS * D_MODEL / 4;
    const int nw4 = (int)(WSZ / 4);

    split_fp32<<<nx4 / 256, 256>>>(x,  pxh, pxl, nx4);
    split_fp32<<<nw4 / 256, 256>>>(Wq, pWh + 0 * WSZ, pWl + 0 * WSZ, nw4);
    split_fp32<<<nw4 / 256, 256>>>(Wk, pWh + 1 * WSZ, pWl + 1 * WSZ, nw4);
    split_fp32<<<nw4 / 256, 256>>>(Wv, pWh + 2 * WSZ, pWl + 2 * WSZ, nw4);
    split_fp32<<<nw4 / 256, 256>>>(Wo, pWh + 3 * WSZ, pWl + 3 * WSZ, nw4);

    dim3 ggrid(D_MODEL / BN, M_ROWS / BM);
    gemm_wmma<<<ggrid, 256, SMEM_GEMM>>>(pxh, pxl, pWh + 0 * WSZ, pWl + 0 * WSZ, pQ, 1);
    gemm_wmma<<<ggrid, 256, SMEM_GEMM>>>(pxh, pxl, pWh + 1 * WSZ, pWl + 1 * WSZ, pK, 1);
    gemm_wmma<<<ggrid, 256, SMEM_GEMM>>>(pxh, pxl, pWh + 2 * WSZ, pWl + 2 * WSZ, pV, 1);

    dim3 agrid(S_ / 64, B_ * NUM_HEADS);
    attn_wmma<<<agrid, 256, SMEM_ATTN>>>(pQ, pK, pV, pA);

    split_fp32<<<nx4 / 256, 256>>>(pA, pAh, pAl, nx4);
    gemm_wmma<<<ggrid, 256, SMEM_GEMM>>>(pAh, pAl, pWh + 3 * WSZ, pWl + 3 * WSZ, out, 0);
}